// round 1
// baseline (speedup 1.0000x reference)
#include <cuda_runtime.h>
#include <math.h>
#include <math_constants.h>

#define FULL 0xffffffffu

__device__ __forceinline__ float warp_sum(float v) {
#pragma unroll
    for (int o = 16; o > 0; o >>= 1) v += __shfl_xor_sync(FULL, v, o);
    return v;
}
__device__ __forceinline__ float warp_max(float v) {
#pragma unroll
    for (int o = 16; o > 0; o >>= 1) v = fmaxf(v, __shfl_xor_sync(FULL, v, o));
    return v;
}

// ---- scratch (allocation-free: __device__ globals) ----
__device__ float g_kv[32 * 129 * 64];   // row 0: target emb, rows 1..128: map emb
__device__ float g_Q[32 * 128 * 64];
__device__ float g_K[32 * 129 * 64];
__device__ float g_V[32 * 129 * 64];

// ============================================================
// Kernel 1: map local graph.  One block per (b, m).
// Fused: x@W1+b1 -> LN -> relu -> @W2+b2 -> LN -> relu -> max over P rows.
// Output halves are identical (see analysis): write max to both.
// ============================================================
__global__ __launch_bounds__(640) void k_map_graph(
    const float* __restrict__ xs,
    const float* __restrict__ W1, const float* __restrict__ b1,
    const float* __restrict__ g1, const float* __restrict__ be1,
    const float* __restrict__ W2, const float* __restrict__ b2,
    const float* __restrict__ g2, const float* __restrict__ be2)
{
    int bm = blockIdx.x;              // b*128 + m
    int b = bm >> 7, m = bm & 127;
    int h = threadIdx.x;              // channel 0..31 (lane)
    int i = threadIdx.y;              // row 0..19
    int tid = i * 32 + h;

    __shared__ float sx[20][16];
    __shared__ float sW1[16][32];
    __shared__ float sW2[32][32];
    __shared__ float sb1[32], sg1[32], sbe1[32], sb2[32], sg2[32], sbe2[32];
    __shared__ float se[20][32];

    const float* xrow = xs + (size_t)bm * 320;
    if (tid < 320) { sx[tid >> 4][tid & 15] = xrow[tid]; }
    if (tid < 512) { sW1[tid >> 5][tid & 31] = W1[tid]; }
    for (int t = tid; t < 1024; t += 640) sW2[t >> 5][t & 31] = W2[t];
    if (i == 0) {
        sb1[h] = b1[h]; sg1[h] = g1[h]; sbe1[h] = be1[h];
        sb2[h] = b2[h]; sg2[h] = g2[h]; sbe2[h] = be2[h];
    }
    __syncthreads();

    float acc = sb1[h];
#pragma unroll
    for (int k = 0; k < 16; k++) acc = fmaf(sx[i][k], sW1[k][h], acc);
    float mu  = warp_sum(acc) * 0.03125f;
    float dd  = acc - mu;
    float var = warp_sum(dd * dd) * 0.03125f;
    float r   = fmaxf(fmaf(dd * rsqrtf(var + 1e-5f), sg1[h], sbe1[h]), 0.f);

    float acc2 = sb2[h];
#pragma unroll
    for (int k = 0; k < 32; k++)
        acc2 = fmaf(__shfl_sync(FULL, r, k), sW2[k][h], acc2);
    mu  = warp_sum(acc2) * 0.03125f;
    dd  = acc2 - mu;
    var = warp_sum(dd * dd) * 0.03125f;
    float e = fmaxf(fmaf(dd * rsqrtf(var + 1e-5f), sg2[h], sbe2[h]), 0.f);

    se[i][h] = e;
    __syncthreads();

    if (i == 0) {
        float mx = se[0][h];
#pragma unroll
        for (int j = 1; j < 20; j++) mx = fmaxf(mx, se[j][h]);
        float* dst = g_kv + ((size_t)b * 129 + 1 + m) * 64;
        dst[h] = mx;
        dst[32 + h] = mx;
    }
}

// ============================================================
// Kernel 2: agent local graph, ONLY agent a=0 (all that's consumed).
// One block per batch; rows = T = 32.
// ============================================================
__global__ __launch_bounds__(1024) void k_agent_graph(
    const float* __restrict__ xs,
    const float* __restrict__ W1, const float* __restrict__ b1,
    const float* __restrict__ g1, const float* __restrict__ be1,
    const float* __restrict__ W2, const float* __restrict__ b2,
    const float* __restrict__ g2, const float* __restrict__ be2)
{
    int b = blockIdx.x;
    int h = threadIdx.x;
    int i = threadIdx.y;
    int tid = i * 32 + h;

    __shared__ float sx[32][4];
    __shared__ float sW1[4][32];
    __shared__ float sW2[32][32];
    __shared__ float sb1[32], sg1[32], sbe1[32], sb2[32], sg2[32], sbe2[32];
    __shared__ float se[32][32];

    const float* xrow = xs + (size_t)b * (32 * 32 * 4);  // agent a = 0
    if (tid < 128) sx[tid >> 2][tid & 3] = xrow[tid];
    if (tid >= 128 && tid < 256) { int t = tid - 128; sW1[t >> 5][t & 31] = W1[t]; }
    sW2[tid >> 5][tid & 31] = W2[tid];   // exactly 1024 threads
    if (i == 0) {
        sb1[h] = b1[h]; sg1[h] = g1[h]; sbe1[h] = be1[h];
        sb2[h] = b2[h]; sg2[h] = g2[h]; sbe2[h] = be2[h];
    }
    __syncthreads();

    float acc = sb1[h];
#pragma unroll
    for (int k = 0; k < 4; k++) acc = fmaf(sx[i][k], sW1[k][h], acc);
    float mu  = warp_sum(acc) * 0.03125f;
    float dd  = acc - mu;
    float var = warp_sum(dd * dd) * 0.03125f;
    float r   = fmaxf(fmaf(dd * rsqrtf(var + 1e-5f), sg1[h], sbe1[h]), 0.f);

    float acc2 = sb2[h];
#pragma unroll
    for (int k = 0; k < 32; k++)
        acc2 = fmaf(__shfl_sync(FULL, r, k), sW2[k][h], acc2);
    mu  = warp_sum(acc2) * 0.03125f;
    dd  = acc2 - mu;
    var = warp_sum(dd * dd) * 0.03125f;
    float e = fmaxf(fmaf(dd * rsqrtf(var + 1e-5f), sg2[h], sbe2[h]), 0.f);

    se[i][h] = e;
    __syncthreads();

    if (i == 0) {
        float mx = se[0][h];
#pragma unroll
        for (int j = 1; j < 32; j++) mx = fmaxf(mx, se[j][h]);
        float* dst = g_kv + (size_t)b * 129 * 64;   // kv row 0 = target
        dst[h] = mx;
        dst[32 + h] = mx;
    }
}

// ============================================================
// Kernel 3: Q/K/V projection for attention head 0.
// kv rows 0..128 per batch; Q for rows 1..128 (map rows).
// Weights staged in smem, 16 rows per block.
// ============================================================
__global__ __launch_bounds__(256) void k_proj(
    const float* __restrict__ Wq, const float* __restrict__ bq,
    const float* __restrict__ Wk, const float* __restrict__ bk,
    const float* __restrict__ Wv, const float* __restrict__ bv)
{
    int b  = blockIdx.y;
    int r0 = blockIdx.x * 16;
    int tid = threadIdx.x;

    __shared__ float sW[64 * 64];
    __shared__ float sx[16][64];
    __shared__ float sb[64];

    for (int t = tid; t < 16 * 64; t += 256) {
        int rl = t >> 6, d = t & 63;
        int r = r0 + rl;
        sx[rl][d] = (r < 129) ? g_kv[((size_t)b * 129 + r) * 64 + d] : 0.f;
    }

    const float* Ws[3] = {Wq, Wk, Wv};
    const float* bs[3] = {bq, bk, bv};

    for (int pass = 0; pass < 3; pass++) {
        __syncthreads();
        for (int t = tid; t < 4096; t += 256) sW[t] = Ws[pass][t];
        if (tid < 64) sb[tid] = bs[pass][tid];
        __syncthreads();

        int d = tid & 63, rr = tid >> 6;
        for (int rl = rr; rl < 16; rl += 4) {
            int r = r0 + rl;
            if (r >= 129) break;
            if (pass == 0 && r == 0) continue;
            float acc = sb[d];
#pragma unroll
            for (int j = 0; j < 64; j++) acc = fmaf(sx[rl][j], sW[j * 64 + d], acc);
            if (pass == 0)      g_Q[((size_t)b * 128 + (r - 1)) * 64 + d] = acc;
            else if (pass == 1) g_K[((size_t)b * 129 + r) * 64 + d] = acc;
            else                g_V[((size_t)b * 129 + r) * 64 + d] = acc;
        }
    }
}

// ============================================================
// Kernel 4: a2m attention (map queries over [target; map] kv)
// + output projection + residual.  Grid (4 q-tiles, 32 batches).
// ============================================================
#define KVP 65   // row pad to kill bank conflicts on K-dot
constexpr int ATTN_SMEM_FLOATS =
    129 * KVP      // sK
  + 129 * KVP      // sV
  + 32 * 64        // sQ
  + 32 * 132       // sS (scores, padded)
  + 32 * 64        // sO
  + 64 * 64        // sWo
  + 64;            // sbo
constexpr int ATTN_SMEM_BYTES = ATTN_SMEM_FLOATS * 4;

__global__ __launch_bounds__(256) void k_attn(
    const float* __restrict__ Wo, const float* __restrict__ bo,
    float* __restrict__ out)
{
    extern __shared__ float smem[];
    float* sK  = smem;
    float* sV  = sK + 129 * KVP;
    float* sQ  = sV + 129 * KVP;
    float* sS  = sQ + 32 * 64;
    float* sO  = sS + 32 * 132;
    float* sWo = sO + 32 * 64;
    float* sbo = sWo + 64 * 64;

    int b  = blockIdx.y;
    int q0 = blockIdx.x * 32;
    int tid = threadIdx.x;

    for (int t = tid; t < 129 * 64; t += 256) {
        int r = t >> 6, d = t & 63;
        sK[r * KVP + d] = g_K[((size_t)b * 129 + r) * 64 + d];
        sV[r * KVP + d] = g_V[((size_t)b * 129 + r) * 64 + d];
    }
    for (int t = tid; t < 32 * 64; t += 256)
        sQ[t] = g_Q[((size_t)b * 128 + q0) * 64 + t];
    for (int t = tid; t < 4096; t += 256) sWo[t] = Wo[t];
    if (tid < 64) sbo[tid] = bo[tid];
    __syncthreads();

    // scores: 32 q x 129 k
    for (int t = tid; t < 32 * 129; t += 256) {
        int q = t / 129, k = t - q * 129;
        float acc = 0.f;
#pragma unroll
        for (int j = 0; j < 64; j++)
            acc = fmaf(sQ[q * 64 + j], sK[k * KVP + j], acc);
        sS[q * 132 + k] = acc * 0.125f;   // / sqrt(64)
    }
    __syncthreads();

    // softmax: each of 8 warps handles 4 rows
    int w = tid >> 5, lane = tid & 31;
    for (int q = w * 4; q < w * 4 + 4; q++) {
        float mx = -CUDART_INF_F;
        for (int k = lane; k < 129; k += 32) mx = fmaxf(mx, sS[q * 132 + k]);
        mx = warp_max(mx);
        float s = 0.f;
        for (int k = lane; k < 129; k += 32) {
            float e = __expf(sS[q * 132 + k] - mx);
            sS[q * 132 + k] = e;
            s += e;
        }
        s = warp_sum(s);
        float inv = 1.f / s;
        for (int k = lane; k < 129; k += 32) sS[q * 132 + k] *= inv;
    }
    __syncthreads();

    // attn @ V
    int d = tid & 63, qg = tid >> 6;
    for (int q = qg; q < 32; q += 4) {
        float acc = 0.f;
        for (int k = 0; k < 129; k++)
            acc = fmaf(sS[q * 132 + k], sV[k * KVP + d], acc);
        sO[q * 64 + d] = acc;
    }
    __syncthreads();

    // @ Wo + bo + residual -> d_out rows 1..128
    for (int q = qg; q < 32; q += 4) {
        float acc = sbo[d];
#pragma unroll
        for (int j = 0; j < 64; j++)
            acc = fmaf(sO[q * 64 + j], sWo[j * 64 + d], acc);
        size_t off = ((size_t)b * 129 + 1 + q0 + q) * 64 + d;
        out[off] = g_kv[off] + acc;
    }
}

// ============================================================
// Kernel 5: target row.  t_a = (target@Wv1+bv1)@Wo1+bo1
// (softmax over 1 key == 1).  t_m2a uses folded projections:
//   u = Wk2 . Q2;  score_k = (me_k . u + Q2.bk2)/8
//   attn@V2 = (sum_k a_k me_k) @ Wv2 + bv2  (sum a_k = 1)
// me = UPDATED map emb (d_out rows 1..128).
// ============================================================
#define MEP 65
__global__ __launch_bounds__(128) void k_target(
    const float* __restrict__ Wq2, const float* __restrict__ bq2,
    const float* __restrict__ Wk2, const float* __restrict__ bk2,
    const float* __restrict__ Wv2, const float* __restrict__ bv2,
    const float* __restrict__ Wo2, const float* __restrict__ bo2,
    const float* __restrict__ Wv1, const float* __restrict__ bv1,
    const float* __restrict__ Wo1, const float* __restrict__ bo1,
    float* __restrict__ out)
{
    int b = blockIdx.x;
    int tid = threadIdx.x;

    __shared__ float sme[128 * MEP];
    __shared__ float st[64], sv[64], sta[64], sQ2[64], su[64], sw[64], stmp[64];
    __shared__ float sA[128];
    __shared__ float sredA[4], sredB[4];
    __shared__ float sc;

    if (tid < 64) st[tid] = g_kv[(size_t)b * 129 * 64 + tid];
    for (int t = tid; t < 128 * 64; t += 128) {
        int r = t >> 6, d = t & 63;
        sme[r * MEP + d] = out[((size_t)b * 129 + 1 + r) * 64 + d];
    }
    __syncthreads();

    // stage A: v1 (t_a path) and Q2 in parallel halves
    if (tid < 64) {
        float acc = bv1[tid];
#pragma unroll
        for (int j = 0; j < 64; j++) acc = fmaf(st[j], Wv1[j * 64 + tid], acc);
        sv[tid] = acc;
    } else {
        int d = tid - 64;
        float acc = bq2[d];
#pragma unroll
        for (int j = 0; j < 64; j++) acc = fmaf(st[j], Wq2[j * 64 + d], acc);
        sQ2[d] = acc;
    }
    __syncthreads();

    // stage B: t_a = v1 @ Wo1 + bo1 ; u[j] = Wk2[j,:] . Q2
    if (tid < 64) {
        float acc = bo1[tid];
#pragma unroll
        for (int j = 0; j < 64; j++) acc = fmaf(sv[j], Wo1[j * 64 + tid], acc);
        sta[tid] = acc;
    } else {
        int j = tid - 64;
        float acc = 0.f;
#pragma unroll
        for (int d = 0; d < 64; d++) acc = fmaf(sQ2[d], Wk2[j * 64 + d], acc);
        su[j] = acc;
    }
    __syncthreads();

    // c = Q2 . bk2
    if (tid < 32) {
        float acc = 0.f;
        for (int d = tid; d < 64; d += 32) acc = fmaf(sQ2[d], bk2[d], acc);
        acc = warp_sum(acc);
        if (tid == 0) sc = acc;
    }
    __syncthreads();

    // scores over 128 map rows (thread k = row k)
    float sk = 0.f;
#pragma unroll
    for (int j = 0; j < 64; j++) sk = fmaf(sme[tid * MEP + j], su[j], sk);
    sk = (sk + sc) * 0.125f;

    // block softmax (128 elems)
    float mx = warp_max(sk);
    if ((tid & 31) == 0) sredA[tid >> 5] = mx;
    __syncthreads();
    mx = fmaxf(fmaxf(sredA[0], sredA[1]), fmaxf(sredA[2], sredA[3]));
    float ex = __expf(sk - mx);
    float ssum = warp_sum(ex);
    if ((tid & 31) == 0) sredB[tid >> 5] = ssum;
    __syncthreads();
    float tot = sredB[0] + sredB[1] + sredB[2] + sredB[3];
    sA[tid] = ex / tot;
    __syncthreads();

    // w[j] = sum_k a_k * me[k][j]
    if (tid < 64) {
        float acc = 0.f;
        for (int k = 0; k < 128; k++) acc = fmaf(sA[k], sme[k * MEP + tid], acc);
        sw[tid] = acc;
    }
    __syncthreads();

    // tmp = w @ Wv2 + bv2
    if (tid < 64) {
        float acc = bv2[tid];
#pragma unroll
        for (int j = 0; j < 64; j++) acc = fmaf(sw[j], Wv2[j * 64 + tid], acc);
        stmp[tid] = acc;
    }
    __syncthreads();

    // out row 0 = t_a + tmp @ Wo2 + bo2
    if (tid < 64) {
        float acc = bo2[tid];
#pragma unroll
        for (int j = 0; j < 64; j++) acc = fmaf(stmp[j], Wo2[j * 64 + tid], acc);
        out[(size_t)b * 129 * 64 + tid] = sta[tid] + acc;
    }
}

// ============================================================
extern "C" void kernel_launch(void* const* d_in, const int* in_sizes, int n_in,
                              void* d_out, int out_size)
{
    const float* map_states   = (const float*)d_in[0];
    const float* agent_states = (const float*)d_in[1];
    const float* m_W1 = (const float*)d_in[2];
    const float* m_b1 = (const float*)d_in[3];
    const float* m_g1 = (const float*)d_in[4];
    const float* m_be1= (const float*)d_in[5];
    const float* m_W2 = (const float*)d_in[6];
    const float* m_b2 = (const float*)d_in[7];
    const float* m_g2 = (const float*)d_in[8];
    const float* m_be2= (const float*)d_in[9];
    const float* a_W1 = (const float*)d_in[10];
    const float* a_b1 = (const float*)d_in[11];
    const float* a_g1 = (const float*)d_in[12];
    const float* a_be1= (const float*)d_in[13];
    const float* a_W2 = (const float*)d_in[14];
    const float* a_b2 = (const float*)d_in[15];
    const float* a_g2 = (const float*)d_in[16];
    const float* a_be2= (const float*)d_in[17];
    const float* att_Wq = (const float*)d_in[18];
    const float* att_bq = (const float*)d_in[19];
    const float* att_Wk = (const float*)d_in[20];
    const float* att_bk = (const float*)d_in[21];
    const float* att_Wv = (const float*)d_in[22];
    const float* att_bv = (const float*)d_in[23];
    const float* att_Wo = (const float*)d_in[24];
    const float* att_bo = (const float*)d_in[25];
    float* out = (float*)d_out;

    // idempotent, cheap, graph-capture safe (not a stream op)
    cudaFuncSetAttribute(k_attn, cudaFuncAttributeMaxDynamicSharedMemorySize,
                         ATTN_SMEM_BYTES);

    k_map_graph<<<4096, dim3(32, 20)>>>(map_states,
        m_W1, m_b1, m_g1, m_be1, m_W2, m_b2, m_g2, m_be2);

    k_agent_graph<<<32, dim3(32, 32)>>>(agent_states,
        a_W1, a_b1, a_g1, a_be1, a_W2, a_b2, a_g2, a_be2);

    k_proj<<<dim3(9, 32), 256>>>(
        att_Wq + 0 * 4096, att_bq + 0 * 64,
        att_Wk + 0 * 4096, att_bk + 0 * 64,
        att_Wv + 0 * 4096, att_bv + 0 * 64);

    k_attn<<<dim3(4, 32), 256, ATTN_SMEM_BYTES>>>(
        att_Wo + 0 * 4096, att_bo + 0 * 64, out);

    k_target<<<32, 128>>>(
        att_Wq + 2 * 4096, att_bq + 2 * 64,
        att_Wk + 2 * 4096, att_bk + 2 * 64,
        att_Wv + 2 * 4096, att_bv + 2 * 64,
        att_Wo + 2 * 4096, att_bo + 2 * 64,
        att_Wv + 1 * 4096, att_bv + 1 * 64,
        att_Wo + 1 * 4096, att_bo + 1 * 64,
        out);
}

// round 2
// speedup vs baseline: 1.4122x; 1.4122x over previous
#include <cuda_runtime.h>
#include <math.h>
#include <math_constants.h>

#define FULL 0xffffffffu

__device__ __forceinline__ float warp_sum(float v) {
#pragma unroll
    for (int o = 16; o > 0; o >>= 1) v += __shfl_xor_sync(FULL, v, o);
    return v;
}
__device__ __forceinline__ float warp_max(float v) {
#pragma unroll
    for (int o = 16; o > 0; o >>= 1) v = fmaxf(v, __shfl_xor_sync(FULL, v, o));
    return v;
}

// ---- scratch (allocation-free: __device__ globals) ----
__device__ float g_kv[32 * 129 * 64];   // row 0: target emb, rows 1..128: map emb
__device__ float g_Q[32 * 128 * 64];
__device__ float g_K[32 * 129 * 64];
__device__ float g_V[32 * 129 * 64];

// ============================================================
// Kernel 1 (merged): local graphs.
//   blocks [0,1024): map graph, 4 (b,m) pairs per block (amortize weights)
//   blocks [1024,1056): agent graph for agent 0 of batch b
// Output halves identical (nb-branch collapses to the same channel max).
// ============================================================
__global__ __launch_bounds__(640) void k_graph(
    const float* __restrict__ mxs,
    const float* __restrict__ mW1, const float* __restrict__ mb1,
    const float* __restrict__ mg1, const float* __restrict__ mbe1,
    const float* __restrict__ mW2, const float* __restrict__ mb2,
    const float* __restrict__ mg2, const float* __restrict__ mbe2,
    const float* __restrict__ axs,
    const float* __restrict__ aW1, const float* __restrict__ ab1,
    const float* __restrict__ ag1, const float* __restrict__ abe1,
    const float* __restrict__ aW2, const float* __restrict__ ab2,
    const float* __restrict__ ag2, const float* __restrict__ abe2)
{
    int h = threadIdx.x;              // channel 0..31 (lane)
    int i = threadIdx.y;              // warp/row id 0..19
    int tid = i * 32 + h;

    if (blockIdx.x < 1024) {
        // ---------------- map path ----------------
        __shared__ float sx[4][20][16];
        __shared__ float sW1[16][32];
        __shared__ float sW2[32][32];
        __shared__ float sb1[32], sg1[32], sbe1[32], sb2[32], sg2[32], sbe2[32];
        __shared__ float se[20][32];

        int bm0 = blockIdx.x * 4;
        const float* xg = mxs + (size_t)bm0 * 320;
        for (int t = tid; t < 1280; t += 640) ((float*)sx)[t] = xg[t];
        if (tid < 512) ((float*)sW1)[tid] = mW1[tid];
        for (int t = tid; t < 1024; t += 640) ((float*)sW2)[t] = mW2[t];
        if (i == 0) {
            sb1[h] = mb1[h]; sg1[h] = mg1[h]; sbe1[h] = mbe1[h];
            sb2[h] = mb2[h]; sg2[h] = mg2[h]; sbe2[h] = mbe2[h];
        }
        __syncthreads();

        for (int mi = 0; mi < 4; mi++) {
            float acc = sb1[h];
#pragma unroll
            for (int k = 0; k < 16; k++) acc = fmaf(sx[mi][i][k], sW1[k][h], acc);
            float mu  = warp_sum(acc) * 0.03125f;
            float dd  = acc - mu;
            float var = warp_sum(dd * dd) * 0.03125f;
            float r   = fmaxf(fmaf(dd * rsqrtf(var + 1e-5f), sg1[h], sbe1[h]), 0.f);

            float acc2 = sb2[h];
#pragma unroll
            for (int k = 0; k < 32; k++)
                acc2 = fmaf(__shfl_sync(FULL, r, k), sW2[k][h], acc2);
            mu  = warp_sum(acc2) * 0.03125f;
            dd  = acc2 - mu;
            var = warp_sum(dd * dd) * 0.03125f;
            float e = fmaxf(fmaf(dd * rsqrtf(var + 1e-5f), sg2[h], sbe2[h]), 0.f);

            se[i][h] = e;
            __syncthreads();

            if (i == 0) {
                float mx = se[0][h];
#pragma unroll
                for (int j = 1; j < 20; j++) mx = fmaxf(mx, se[j][h]);
                int bm = bm0 + mi;
                int b = bm >> 7, m = bm & 127;
                float* dst = g_kv + ((size_t)b * 129 + 1 + m) * 64;
                dst[h] = mx;
                dst[32 + h] = mx;
            }
            __syncthreads();
        }
    } else {
        // ---------------- agent path (agent 0 only) ----------------
        __shared__ float ax[32][4];
        __shared__ float aW1s[4][32];
        __shared__ float aW2s[32][32];
        __shared__ float ab1s[32], ag1s[32], abe1s[32], ab2s[32], ag2s[32], abe2s[32];
        __shared__ float ase[32][32];

        int b = blockIdx.x - 1024;
        const float* xrow = axs + (size_t)b * (32 * 32 * 4);  // agent a = 0
        if (tid < 128) ((float*)ax)[tid] = xrow[tid];
        if (tid >= 128 && tid < 256) ((float*)aW1s)[tid - 128] = aW1[tid - 128];
        for (int t = tid; t < 1024; t += 640) ((float*)aW2s)[t] = aW2[t];
        if (i == 0) {
            ab1s[h] = ab1[h]; ag1s[h] = ag1[h]; abe1s[h] = abe1[h];
            ab2s[h] = ab2[h]; ag2s[h] = ag2[h]; abe2s[h] = abe2[h];
        }
        __syncthreads();

        // warp i handles row i, and row i+20 when i<12 (warp-uniform branch)
#pragma unroll
        for (int pass = 0; pass < 2; pass++) {
            int row = i + pass * 20;
            if (row < 32) {
                float acc = ab1s[h];
#pragma unroll
                for (int k = 0; k < 4; k++) acc = fmaf(ax[row][k], aW1s[k][h], acc);
                float mu  = warp_sum(acc) * 0.03125f;
                float dd  = acc - mu;
                float var = warp_sum(dd * dd) * 0.03125f;
                float r   = fmaxf(fmaf(dd * rsqrtf(var + 1e-5f), ag1s[h], abe1s[h]), 0.f);

                float acc2 = ab2s[h];
#pragma unroll
                for (int k = 0; k < 32; k++)
                    acc2 = fmaf(__shfl_sync(FULL, r, k), aW2s[k][h], acc2);
                mu  = warp_sum(acc2) * 0.03125f;
                dd  = acc2 - mu;
                var = warp_sum(dd * dd) * 0.03125f;
                float e = fmaxf(fmaf(dd * rsqrtf(var + 1e-5f), ag2s[h], abe2s[h]), 0.f);
                ase[row][h] = e;
            }
        }
        __syncthreads();

        if (i == 0) {
            float mx = ase[0][h];
#pragma unroll
            for (int j = 1; j < 32; j++) mx = fmaxf(mx, ase[j][h]);
            float* dst = g_kv + (size_t)b * 129 * 64;   // kv row 0 = target
            dst[h] = mx;
            dst[32 + h] = mx;
        }
    }
}

// ============================================================
// Kernel 2: Q/K/V projection, head 0. All three weights in smem,
// float4 inner loops. Thread = (row, d4). 16 rows/block.
// ============================================================
constexpr int PROJ_SMEM_FLOATS = 3 * 4096 + 16 * 64 + 3 * 64;
constexpr int PROJ_SMEM_BYTES = PROJ_SMEM_FLOATS * 4;

__global__ __launch_bounds__(256) void k_proj(
    const float* __restrict__ Wq, const float* __restrict__ bq,
    const float* __restrict__ Wk, const float* __restrict__ bk,
    const float* __restrict__ Wv, const float* __restrict__ bv)
{
    extern __shared__ float psm[];
    float* sW = psm;              // 3 * 4096
    float* sx = sW + 12288;       // 16 * 64
    float* sb = sx + 1024;        // 3 * 64

    int b  = blockIdx.y;
    int r0 = blockIdx.x * 16;
    int tid = threadIdx.x;

    for (int t = tid; t < 1024; t += 256) {
        ((float4*)sW)[t]        = ((const float4*)Wq)[t];
        ((float4*)sW)[1024 + t] = ((const float4*)Wk)[t];
        ((float4*)sW)[2048 + t] = ((const float4*)Wv)[t];
    }
    if (tid < 64) { sb[tid] = bq[tid]; sb[64 + tid] = bk[tid]; sb[128 + tid] = bv[tid]; }
    {
        int rl = tid >> 4, d4 = tid & 15;
        int r = r0 + rl;
        float4 v = make_float4(0.f, 0.f, 0.f, 0.f);
        if (r < 129) v = ((const float4*)g_kv)[((size_t)b * 129 + r) * 16 + d4];
        ((float4*)sx)[tid] = v;
    }
    __syncthreads();

    int rl = tid >> 4, d4 = tid & 15;
    int r = r0 + rl;

#pragma unroll
    for (int p = 0; p < 3; p++) {
        if (r < 129 && !(p == 0 && r == 0)) {
            float4 acc = ((const float4*)sb)[p * 16 + d4];
            const float* xr = sx + rl * 64;
            const float4* W4 = (const float4*)sW + p * 1024;
#pragma unroll 8
            for (int j = 0; j < 64; j++) {
                float x = xr[j];
                float4 w = W4[j * 16 + d4];
                acc.x = fmaf(x, w.x, acc.x);
                acc.y = fmaf(x, w.y, acc.y);
                acc.z = fmaf(x, w.z, acc.z);
                acc.w = fmaf(x, w.w, acc.w);
            }
            if (p == 0)      ((float4*)g_Q)[((size_t)b * 128 + (r - 1)) * 16 + d4] = acc;
            else if (p == 1) ((float4*)g_K)[((size_t)b * 129 + r) * 16 + d4] = acc;
            else             ((float4*)g_V)[((size_t)b * 129 + r) * 16 + d4] = acc;
        }
        __syncthreads();   // cheap; keeps weight region coherent semantics simple
    }
}

// ============================================================
// Kernel 3: a2m attention + Wo + residual.  512 threads,
// float4 everywhere, conflict-free pads (K/V/O stride 68, S stride 132).
// ============================================================
#define KVP 68
constexpr int ATTN_SMEM_FLOATS =
    129 * KVP      // sK
  + 129 * KVP      // sV
  + 32 * 64        // sQ
  + 32 * 132       // sS
  + 32 * KVP       // sO
  + 64 * 64        // sWo
  + 64;            // sbo
constexpr int ATTN_SMEM_BYTES = ATTN_SMEM_FLOATS * 4;

__global__ __launch_bounds__(512) void k_attn(
    const float* __restrict__ Wo, const float* __restrict__ bo,
    float* __restrict__ out)
{
    extern __shared__ float smem[];
    float* sK  = smem;
    float* sV  = sK + 129 * KVP;
    float* sQ  = sV + 129 * KVP;
    float* sS  = sQ + 32 * 64;
    float* sO  = sS + 32 * 132;
    float* sWo = sO + 32 * KVP;
    float* sbo = sWo + 64 * 64;

    int b  = blockIdx.y;
    int q0 = blockIdx.x * 32;
    int tid = threadIdx.x;

    const float4* K4g = (const float4*)(g_K + (size_t)b * 129 * 64);
    const float4* V4g = (const float4*)(g_V + (size_t)b * 129 * 64);
    for (int t = tid; t < 129 * 16; t += 512) {
        int r = t >> 4, d4 = t & 15;
        ((float4*)sK)[r * 17 + d4] = K4g[t];
        ((float4*)sV)[r * 17 + d4] = V4g[t];
    }
    ((float4*)sQ)[tid] = ((const float4*)(g_Q + (size_t)b * 128 * 64))[q0 * 16 + tid];
    for (int t = tid; t < 1024; t += 512) ((float4*)sWo)[t] = ((const float4*)Wo)[t];
    if (tid < 64) sbo[tid] = bo[tid];
    __syncthreads();

    int w = tid >> 5, lane = tid & 31;

    // scores: warp w handles q = 2w, 2w+1; lanes stride k
#pragma unroll
    for (int qq = 0; qq < 2; qq++) {
        int q = w * 2 + qq;
        const float4* q4 = (const float4*)(sQ + q * 64);
        for (int k = lane; k < 129; k += 32) {
            const float4* k4 = (const float4*)(sK + k * KVP);
            float4 a = make_float4(0.f, 0.f, 0.f, 0.f);
#pragma unroll
            for (int j = 0; j < 16; j++) {
                float4 qv = q4[j], kv = k4[j];
                a.x = fmaf(qv.x, kv.x, a.x);
                a.y = fmaf(qv.y, kv.y, a.y);
                a.z = fmaf(qv.z, kv.z, a.z);
                a.w = fmaf(qv.w, kv.w, a.w);
            }
            sS[q * 132 + k] = (a.x + a.y + a.z + a.w) * 0.125f;
        }
    }
    __syncthreads();

    // softmax: warp w handles q = 2w, 2w+1
#pragma unroll
    for (int qq = 0; qq < 2; qq++) {
        int q = w * 2 + qq;
        float mx = -CUDART_INF_F;
        for (int k = lane; k < 129; k += 32) mx = fmaxf(mx, sS[q * 132 + k]);
        mx = warp_max(mx);
        float s = 0.f;
        for (int k = lane; k < 129; k += 32) {
            float e = __expf(sS[q * 132 + k] - mx);
            sS[q * 132 + k] = e;
            s += e;
        }
        s = warp_sum(s);
        float inv = 1.f / s;
        for (int k = lane; k < 129; k += 32) sS[q * 132 + k] *= inv;
    }
    __syncthreads();

    // attn @ V : thread = (q, d4)
    int q = tid >> 4, d4 = tid & 15;
    {
        float4 acc = make_float4(0.f, 0.f, 0.f, 0.f);
        const float4* V4 = (const float4*)sV;
        const float* Sr = sS + q * 132;
#pragma unroll 4
        for (int k = 0; k < 129; k++) {
            float a = Sr[k];
            float4 v = V4[k * 17 + d4];
            acc.x = fmaf(a, v.x, acc.x);
            acc.y = fmaf(a, v.y, acc.y);
            acc.z = fmaf(a, v.z, acc.z);
            acc.w = fmaf(a, v.w, acc.w);
        }
        ((float4*)sO)[q * 17 + d4] = acc;
    }
    __syncthreads();

    // @ Wo + bo + residual
    {
        float4 acc = ((const float4*)sbo)[d4];
        const float* Or = sO + q * KVP;
        const float4* W4 = (const float4*)sWo;
#pragma unroll 8
        for (int j = 0; j < 64; j++) {
            float o = Or[j];
            float4 wv = W4[j * 16 + d4];
            acc.x = fmaf(o, wv.x, acc.x);
            acc.y = fmaf(o, wv.y, acc.y);
            acc.z = fmaf(o, wv.z, acc.z);
            acc.w = fmaf(o, wv.w, acc.w);
        }
        size_t off4 = ((size_t)b * 129 + 1 + q0 + q) * 16 + d4;
        float4 res = ((const float4*)g_kv)[off4];
        ((float4*)out)[off4] = make_float4(res.x + acc.x, res.y + acc.y,
                                           res.z + acc.z, res.w + acc.w);
    }
}

// ============================================================
// Kernel 4: target row.  t_a = (target@Wv1+bv1)@Wo1+bo1.
// t_m2a with folded projections (single query).
// ============================================================
#define MEP 68
__global__ __launch_bounds__(128) void k_target(
    const float* __restrict__ Wq2, const float* __restrict__ bq2,
    const float* __restrict__ Wk2, const float* __restrict__ bk2,
    const float* __restrict__ Wv2, const float* __restrict__ bv2,
    const float* __restrict__ Wo2, const float* __restrict__ bo2,
    const float* __restrict__ Wv1, const float* __restrict__ bv1,
    const float* __restrict__ Wo1, const float* __restrict__ bo1,
    float* __restrict__ out)
{
    int b = blockIdx.x;
    int tid = threadIdx.x;

    __shared__ float4 sme4[128 * 17];
    float* sme = (float*)sme4;
    __shared__ __align__(16) float st[64], sv[64], sta[64], sQ2[64], su[64], sw[64], stmp[64];
    __shared__ float sA[128];
    __shared__ float sredA[4], sredB[4];
    __shared__ float sc;

    if (tid < 64) st[tid] = g_kv[(size_t)b * 129 * 64 + tid];
    for (int t = tid; t < 2048; t += 128) {
        int r = t >> 4, d4 = t & 15;
        sme4[r * 17 + d4] = ((const float4*)out)[((size_t)b * 129 + 1 + r) * 16 + d4];
    }
    __syncthreads();

    // stage A: v1 (t_a path) and Q2 in parallel halves
    if (tid < 64) {
        float acc = bv1[tid];
#pragma unroll
        for (int j = 0; j < 64; j++) acc = fmaf(st[j], Wv1[j * 64 + tid], acc);
        sv[tid] = acc;
    } else {
        int d = tid - 64;
        float acc = bq2[d];
#pragma unroll
        for (int j = 0; j < 64; j++) acc = fmaf(st[j], Wq2[j * 64 + d], acc);
        sQ2[d] = acc;
    }
    __syncthreads();

    // stage B: t_a = v1 @ Wo1 + bo1 ; u[j] = Wk2[j,:] . Q2
    if (tid < 64) {
        float acc = bo1[tid];
#pragma unroll
        for (int j = 0; j < 64; j++) acc = fmaf(sv[j], Wo1[j * 64 + tid], acc);
        sta[tid] = acc;
    } else {
        int j = tid - 64;
        float acc = 0.f;
#pragma unroll
        for (int d = 0; d < 64; d++) acc = fmaf(sQ2[d], Wk2[j * 64 + d], acc);
        su[j] = acc;
    }
    __syncthreads();

    // c = Q2 . bk2
    if (tid < 32) {
        float acc = 0.f;
        for (int d = tid; d < 64; d += 32) acc = fmaf(sQ2[d], bk2[d], acc);
        acc = warp_sum(acc);
        if (tid == 0) sc = acc;
    }
    __syncthreads();

    // scores over 128 map rows (thread = row)
    float sk = 0.f;
    {
        const float4* me4r = (const float4*)(sme + tid * MEP);
        const float4* su4 = (const float4*)su;
#pragma unroll
        for (int j = 0; j < 16; j++) {
            float4 m = me4r[j], u = su4[j];
            sk = fmaf(m.x, u.x, sk);
            sk = fmaf(m.y, u.y, sk);
            sk = fmaf(m.z, u.z, sk);
            sk = fmaf(m.w, u.w, sk);
        }
    }
    sk = (sk + sc) * 0.125f;

    // block softmax (128 elems)
    float mx = warp_max(sk);
    if ((tid & 31) == 0) sredA[tid >> 5] = mx;
    __syncthreads();
    mx = fmaxf(fmaxf(sredA[0], sredA[1]), fmaxf(sredA[2], sredA[3]));
    float ex = __expf(sk - mx);
    float ssum = warp_sum(ex);
    if ((tid & 31) == 0) sredB[tid >> 5] = ssum;
    __syncthreads();
    float tot = sredB[0] + sredB[1] + sredB[2] + sredB[3];
    sA[tid] = ex / tot;
    __syncthreads();

    // w[j] = sum_k a_k * me[k][j]
    if (tid < 64) {
        float acc = 0.f;
        for (int k = 0; k < 128; k++) acc = fmaf(sA[k], sme[k * MEP + tid], acc);
        sw[tid] = acc;
    }
    __syncthreads();

    // tmp = w @ Wv2 + bv2
    if (tid < 64) {
        float acc = bv2[tid];
#pragma unroll
        for (int j = 0; j < 64; j++) acc = fmaf(sw[j], Wv2[j * 64 + tid], acc);
        stmp[tid] = acc;
    }
    __syncthreads();

    // out row 0 = t_a + tmp @ Wo2 + bo2
    if (tid < 64) {
        float acc = bo2[tid];
#pragma unroll
        for (int j = 0; j < 64; j++) acc = fmaf(stmp[j], Wo2[j * 64 + tid], acc);
        out[(size_t)b * 129 * 64 + tid] = sta[tid] + acc;
    }
}

// ============================================================
extern "C" void kernel_launch(void* const* d_in, const int* in_sizes, int n_in,
                              void* d_out, int out_size)
{
    const float* map_states   = (const float*)d_in[0];
    const float* agent_states = (const float*)d_in[1];
    const float* m_W1 = (const float*)d_in[2];
    const float* m_b1 = (const float*)d_in[3];
    const float* m_g1 = (const float*)d_in[4];
    const float* m_be1= (const float*)d_in[5];
    const float* m_W2 = (const float*)d_in[6];
    const float* m_b2 = (const float*)d_in[7];
    const float* m_g2 = (const float*)d_in[8];
    const float* m_be2= (const float*)d_in[9];
    const float* a_W1 = (const float*)d_in[10];
    const float* a_b1 = (const float*)d_in[11];
    const float* a_g1 = (const float*)d_in[12];
    const float* a_be1= (const float*)d_in[13];
    const float* a_W2 = (const float*)d_in[14];
    const float* a_b2 = (const float*)d_in[15];
    const float* a_g2 = (const float*)d_in[16];
    const float* a_be2= (const float*)d_in[17];
    const float* att_Wq = (const float*)d_in[18];
    const float* att_bq = (const float*)d_in[19];
    const float* att_Wk = (const float*)d_in[20];
    const float* att_bk = (const float*)d_in[21];
    const float* att_Wv = (const float*)d_in[22];
    const float* att_bv = (const float*)d_in[23];
    const float* att_Wo = (const float*)d_in[24];
    const float* att_bo = (const float*)d_in[25];
    float* out = (float*)d_out;

    cudaFuncSetAttribute(k_attn, cudaFuncAttributeMaxDynamicSharedMemorySize,
                         ATTN_SMEM_BYTES);
    cudaFuncSetAttribute(k_proj, cudaFuncAttributeMaxDynamicSharedMemorySize,
                         PROJ_SMEM_BYTES);

    k_graph<<<1056, dim3(32, 20)>>>(
        map_states, m_W1, m_b1, m_g1, m_be1, m_W2, m_b2, m_g2, m_be2,
        agent_states, a_W1, a_b1, a_g1, a_be1, a_W2, a_b2, a_g2, a_be2);

    k_proj<<<dim3(9, 32), 256, PROJ_SMEM_BYTES>>>(
        att_Wq + 0 * 4096, att_bq + 0 * 64,
        att_Wk + 0 * 4096, att_bk + 0 * 64,
        att_Wv + 0 * 4096, att_bv + 0 * 64);

    k_attn<<<dim3(4, 32), 512, ATTN_SMEM_BYTES>>>(
        att_Wo + 0 * 4096, att_bo + 0 * 64, out);

    k_target<<<32, 128>>>(
        att_Wq + 2 * 4096, att_bq + 2 * 64,
        att_Wk + 2 * 4096, att_bk + 2 * 64,
        att_Wv + 2 * 4096, att_bv + 2 * 64,
        att_Wo + 2 * 4096, att_bo + 2 * 64,
        att_Wv + 1 * 4096, att_bv + 1 * 64,
        att_Wo + 1 * 4096, att_bo + 1 * 64,
        out);
}

// round 3
// speedup vs baseline: 1.4856x; 1.0520x over previous
#include <cuda_runtime.h>
#include <math.h>
#include <math_constants.h>

#define FULL 0xffffffffu

__device__ __forceinline__ float warp_sum(float v) {
#pragma unroll
    for (int o = 16; o > 0; o >>= 1) v += __shfl_xor_sync(FULL, v, o);
    return v;
}
__device__ __forceinline__ float warp_max(float v) {
#pragma unroll
    for (int o = 16; o > 0; o >>= 1) v = fmaxf(v, __shfl_xor_sync(FULL, v, o));
    return v;
}

// ---- scratch (allocation-free: __device__ globals) ----
__device__ float g_kv[32 * 129 * 64];   // row 0: target emb, rows 1..128: map emb
__device__ float g_Q[32 * 128 * 64];
__device__ float g_K[32 * 129 * 64];
__device__ float g_V[32 * 129 * 64];
__device__ float g_M1[64 * 64], g_c1[64];   // Wv1@Wo1, bv1@Wo1+bo1
__device__ float g_M2[64 * 64], g_c2[64];   // Wv2@Wo2, bv2@Wo2+bo2
__device__ float g_ta[32 * 64];             // t_a per batch
__device__ float g_u[32 * 64];              // folded K-projection vector
__device__ float g_csc[32];                 // Q2 . bk2
__device__ int   g_cnt[32];                 // last-block counter (reset in k_proj)

// ============================================================
// Kernel 1: local graphs + weight-fold matrices.
//   blocks [0,1024): map graph, 4 (b,m) per block
//   [1024,1056): agent graph, agent 0 of batch b
//   [1056,1072): M1/M2 = Wv@Wo folds (8 rows per block) + c1/c2
// ============================================================
__global__ __launch_bounds__(640) void k_graph(
    const float* __restrict__ mxs,
    const float* __restrict__ mW1, const float* __restrict__ mb1,
    const float* __restrict__ mg1, const float* __restrict__ mbe1,
    const float* __restrict__ mW2, const float* __restrict__ mb2,
    const float* __restrict__ mg2, const float* __restrict__ mbe2,
    const float* __restrict__ axs,
    const float* __restrict__ aW1, const float* __restrict__ ab1,
    const float* __restrict__ ag1, const float* __restrict__ abe1,
    const float* __restrict__ aW2, const float* __restrict__ ab2,
    const float* __restrict__ ag2, const float* __restrict__ abe2,
    const float* __restrict__ att_Wv, const float* __restrict__ att_bv,
    const float* __restrict__ att_Wo, const float* __restrict__ att_bo)
{
    int h = threadIdx.x;              // lane / channel
    int i = threadIdx.y;              // warp id 0..19
    int tid = i * 32 + h;

    if (blockIdx.x < 1024) {
        // ---------------- map path ----------------
        __shared__ float sx[4][20][16];
        __shared__ float sW1[16][32];
        __shared__ float sW2[32][32];
        __shared__ float sb1[32], sg1[32], sbe1[32], sb2[32], sg2[32], sbe2[32];
        __shared__ float se[4][20][32];

        int bm0 = blockIdx.x * 4;
        const float* xg = mxs + (size_t)bm0 * 320;
        for (int t = tid; t < 1280; t += 640) ((float*)sx)[t] = xg[t];
        if (tid < 512) ((float*)sW1)[tid] = mW1[tid];
        for (int t = tid; t < 1024; t += 640) ((float*)sW2)[t] = mW2[t];
        if (i == 0) {
            sb1[h] = mb1[h]; sg1[h] = mg1[h]; sbe1[h] = mbe1[h];
            sb2[h] = mb2[h]; sg2[h] = mg2[h]; sbe2[h] = mbe2[h];
        }
        __syncthreads();

#pragma unroll
        for (int mi = 0; mi < 4; mi++) {
            float acc = sb1[h];
#pragma unroll
            for (int k = 0; k < 16; k++) acc = fmaf(sx[mi][i][k], sW1[k][h], acc);
            float mu  = warp_sum(acc) * 0.03125f;
            float dd  = acc - mu;
            float var = warp_sum(dd * dd) * 0.03125f;
            float r   = fmaxf(fmaf(dd * rsqrtf(var + 1e-5f), sg1[h], sbe1[h]), 0.f);

            float acc2 = sb2[h];
#pragma unroll
            for (int k = 0; k < 32; k++)
                acc2 = fmaf(__shfl_sync(FULL, r, k), sW2[k][h], acc2);
            mu  = warp_sum(acc2) * 0.03125f;
            dd  = acc2 - mu;
            var = warp_sum(dd * dd) * 0.03125f;
            se[mi][i][h] = fmaxf(fmaf(dd * rsqrtf(var + 1e-5f), sg2[h], sbe2[h]), 0.f);
        }
        __syncthreads();

        if (i < 4) {
            int mi = i;
            float mx = se[mi][0][h];
#pragma unroll
            for (int j = 1; j < 20; j++) mx = fmaxf(mx, se[mi][j][h]);
            int bm = bm0 + mi;
            int b = bm >> 7, m = bm & 127;
            float* dst = g_kv + ((size_t)b * 129 + 1 + m) * 64;
            dst[h] = mx;
            dst[32 + h] = mx;
        }
    } else if (blockIdx.x < 1056) {
        // ---------------- agent path (agent 0) ----------------
        __shared__ float ax[32][4];
        __shared__ float aW1s[4][32];
        __shared__ float aW2s[32][32];
        __shared__ float ab1s[32], ag1s[32], abe1s[32], ab2s[32], ag2s[32], abe2s[32];
        __shared__ float ase[32][32];

        int b = blockIdx.x - 1024;
        const float* xrow = axs + (size_t)b * (32 * 32 * 4);  // agent a = 0
        if (tid < 128) ((float*)ax)[tid] = xrow[tid];
        if (tid >= 128 && tid < 256) ((float*)aW1s)[tid - 128] = aW1[tid - 128];
        for (int t = tid; t < 1024; t += 640) ((float*)aW2s)[t] = aW2[t];
        if (i == 0) {
            ab1s[h] = ab1[h]; ag1s[h] = ag1[h]; abe1s[h] = abe1[h];
            ab2s[h] = ab2[h]; ag2s[h] = ag2[h]; abe2s[h] = abe2[h];
        }
        __syncthreads();

#pragma unroll
        for (int pass = 0; pass < 2; pass++) {
            int row = i + pass * 20;
            if (row < 32) {
                float acc = ab1s[h];
#pragma unroll
                for (int k = 0; k < 4; k++) acc = fmaf(ax[row][k], aW1s[k][h], acc);
                float mu  = warp_sum(acc) * 0.03125f;
                float dd  = acc - mu;
                float var = warp_sum(dd * dd) * 0.03125f;
                float r   = fmaxf(fmaf(dd * rsqrtf(var + 1e-5f), ag1s[h], abe1s[h]), 0.f);

                float acc2 = ab2s[h];
#pragma unroll
                for (int k = 0; k < 32; k++)
                    acc2 = fmaf(__shfl_sync(FULL, r, k), aW2s[k][h], acc2);
                mu  = warp_sum(acc2) * 0.03125f;
                dd  = acc2 - mu;
                var = warp_sum(dd * dd) * 0.03125f;
                ase[row][h] = fmaxf(fmaf(dd * rsqrtf(var + 1e-5f), ag2s[h], abe2s[h]), 0.f);
            }
        }
        __syncthreads();

        if (i == 0) {
            float mx = ase[0][h];
#pragma unroll
            for (int j = 1; j < 32; j++) mx = fmaxf(mx, ase[j][h]);
            float* dst = g_kv + (size_t)b * 129 * 64;   // kv row 0 = target
            dst[h] = mx;
            dst[32 + h] = mx;
        }
    } else {
        // ---------------- weight-fold: M = Wv@Wo, c = bv@Wo + bo ----------------
        __shared__ float sWo[64 * 64];
        __shared__ float sWv[8 * 64];

        int which = blockIdx.x - 1056;        // 0..15
        int head  = 1 + (which >> 3);         // 1 or 2
        int r0    = (which & 7) * 8;
        const float* Wv = att_Wv + head * 4096;
        const float* Wo = att_Wo + head * 4096;
        const float* bv = att_bv + head * 64;
        const float* bo = att_bo + head * 64;
        float* M    = (head == 1) ? g_M1 : g_M2;
        float* cvec = (head == 1) ? g_c1 : g_c2;

        for (int t = tid; t < 1024; t += 640)
            ((float4*)sWo)[t] = ((const float4*)Wo)[t];
        if (tid < 128)
            ((float4*)sWv)[tid] = ((const float4*)(Wv + r0 * 64))[tid];
        __syncthreads();

        if (tid < 512) {
            int r = tid >> 6, d = tid & 63;
            float acc = 0.f;
#pragma unroll 8
            for (int k = 0; k < 64; k++)
                acc = fmaf(sWv[r * 64 + k], sWo[k * 64 + d], acc);
            M[(r0 + r) * 64 + d] = acc;
        } else if (tid < 576 && r0 == 0) {
            int d = tid - 512;
            float acc = bo[d];
#pragma unroll 8
            for (int k = 0; k < 64; k++)
                acc = fmaf(bv[k], sWo[k * 64 + d], acc);
            cvec[d] = acc;
        }
    }
}

// ============================================================
// Kernel 2: Q/K/V projection (blocks x<9) + target precompute (x==9).
// ============================================================
constexpr int PROJ_SMEM_FLOATS = 3 * 4096 + 16 * 64 + 3 * 64;
constexpr int PROJ_SMEM_BYTES = PROJ_SMEM_FLOATS * 4;

__global__ __launch_bounds__(256) void k_proj(
    const float* __restrict__ Wq, const float* __restrict__ bq,
    const float* __restrict__ Wk, const float* __restrict__ bk,
    const float* __restrict__ Wv, const float* __restrict__ bv,
    const float* __restrict__ Wq2, const float* __restrict__ bq2,
    const float* __restrict__ Wk2, const float* __restrict__ bk2)
{
    extern __shared__ float psm[];
    int b  = blockIdx.y;
    int tid = threadIdx.x;

    if (blockIdx.x < 9) {
        float* sW = psm;              // 3 * 4096
        float* sx = sW + 12288;       // 16 * 64
        float* sb = sx + 1024;        // 3 * 64
        int r0 = blockIdx.x * 16;

        for (int t = tid; t < 1024; t += 256) {
            ((float4*)sW)[t]        = ((const float4*)Wq)[t];
            ((float4*)sW)[1024 + t] = ((const float4*)Wk)[t];
            ((float4*)sW)[2048 + t] = ((const float4*)Wv)[t];
        }
        if (tid < 64) { sb[tid] = bq[tid]; sb[64 + tid] = bk[tid]; sb[128 + tid] = bv[tid]; }
        {
            int rl = tid >> 4, d4 = tid & 15;
            int r = r0 + rl;
            float4 v = make_float4(0.f, 0.f, 0.f, 0.f);
            if (r < 129) v = ((const float4*)g_kv)[((size_t)b * 129 + r) * 16 + d4];
            ((float4*)sx)[tid] = v;
        }
        __syncthreads();

        int rl = tid >> 4, d4 = tid & 15;
        int r = r0 + rl;

#pragma unroll
        for (int p = 0; p < 3; p++) {
            if (r < 129 && !(p == 0 && r == 0)) {
                float4 acc = ((const float4*)sb)[p * 16 + d4];
                const float* xr = sx + rl * 64;
                const float4* W4 = (const float4*)sW + p * 1024;
#pragma unroll 8
                for (int j = 0; j < 64; j++) {
                    float x = xr[j];
                    float4 w = W4[j * 16 + d4];
                    acc.x = fmaf(x, w.x, acc.x);
                    acc.y = fmaf(x, w.y, acc.y);
                    acc.z = fmaf(x, w.z, acc.z);
                    acc.w = fmaf(x, w.w, acc.w);
                }
                if (p == 0)      ((float4*)g_Q)[((size_t)b * 128 + (r - 1)) * 16 + d4] = acc;
                else if (p == 1) ((float4*)g_K)[((size_t)b * 129 + r) * 16 + d4] = acc;
                else             ((float4*)g_V)[((size_t)b * 129 + r) * 16 + d4] = acc;
            }
        }
    } else {
        // ---- target precompute for batch b ----
        float* sW  = psm;             // 4096 (Wq2 staging)
        float* st  = sW + 4096;       // 64
        float* sQ2 = st + 64;         // 64
        float* sp  = sQ2 + 64;        // 4 * 64 partials

        if (tid < 64) st[tid] = g_kv[(size_t)b * 129 * 64 + tid];
        for (int t = tid; t < 1024; t += 256)
            ((float4*)sW)[t] = ((const float4*)Wq2)[t];
        __syncthreads();

        int d = tid & 63, p = tid >> 6;
        {
            float acc = 0.f;
#pragma unroll
            for (int j = p * 16; j < p * 16 + 16; j++)
                acc = fmaf(st[j], sW[j * 64 + d], acc);
            sp[p * 64 + d] = acc;
        }
        __syncthreads();
        if (tid < 64)
            sQ2[tid] = bq2[tid] + sp[tid] + sp[64 + tid] + sp[128 + tid] + sp[192 + tid];
        __syncthreads();

        // c = Q2 . bk2
        if (tid < 32) {
            float a = 0.f;
            for (int dd = tid; dd < 64; dd += 32) a = fmaf(sQ2[dd], bk2[dd], a);
            a = warp_sum(a);
            if (tid == 0) g_csc[b] = a;
        }

        // u[j] = Wk2[j,:] . Q2  (warp per 8 rows, coalesced gmem reads)
        {
            int w = tid >> 5, lane = tid & 31;
            for (int j = w * 8; j < w * 8 + 8; j++) {
                float a = sQ2[lane] * Wk2[j * 64 + lane];
                a = fmaf(sQ2[lane + 32], Wk2[j * 64 + lane + 32], a);
                a = warp_sum(a);
                if (lane == 0) g_u[b * 64 + j] = a;
            }
        }

        // ta = t @ M1 + c1
        if (tid < 64) {
            float acc = g_c1[tid];
#pragma unroll 8
            for (int j = 0; j < 64; j++)
                acc = fmaf(st[j], g_M1[j * 64 + tid], acc);
            g_ta[b * 64 + tid] = acc;
        }

        if (tid == 0) g_cnt[b] = 0;   // reset last-block counter for this launch
    }
}

// ============================================================
// Kernel 3: a2m attention + Wo + residual; last block per batch
// also computes the target row (fused former k_target).
// ============================================================
#define KVP 68
constexpr int ATTN_SMEM_FLOATS =
    129 * KVP      // sK (reused as me-tile in target phase)
  + 129 * KVP      // sV
  + 32 * 64        // sQ (reused as u/w in target phase)
  + 32 * 132       // sS (reused as probs in target phase)
  + 32 * KVP       // sO
  + 64 * 64        // sWo
  + 64;            // sbo
constexpr int ATTN_SMEM_BYTES = ATTN_SMEM_FLOATS * 4;

__global__ __launch_bounds__(512) void k_attn(
    const float* __restrict__ Wo, const float* __restrict__ bo,
    float* __restrict__ out)
{
    extern __shared__ float smem[];
    float* sK  = smem;
    float* sV  = sK + 129 * KVP;
    float* sQ  = sV + 129 * KVP;
    float* sS  = sQ + 32 * 64;
    float* sO  = sS + 32 * 132;
    float* sWo = sO + 32 * KVP;
    float* sbo = sWo + 64 * 64;
    __shared__ int sflag;
    __shared__ float sred[8];

    int b  = blockIdx.y;
    int q0 = blockIdx.x * 32;
    int tid = threadIdx.x;

    const float4* K4g = (const float4*)(g_K + (size_t)b * 129 * 64);
    const float4* V4g = (const float4*)(g_V + (size_t)b * 129 * 64);
    for (int t = tid; t < 129 * 16; t += 512) {
        int r = t >> 4, d4 = t & 15;
        ((float4*)sK)[r * 17 + d4] = K4g[t];
        ((float4*)sV)[r * 17 + d4] = V4g[t];
    }
    ((float4*)sQ)[tid] = ((const float4*)(g_Q + (size_t)b * 128 * 64))[q0 * 16 + tid];
    for (int t = tid; t < 1024; t += 512) ((float4*)sWo)[t] = ((const float4*)Wo)[t];
    if (tid < 64) sbo[tid] = bo[tid];
    __syncthreads();

    int w = tid >> 5, lane = tid & 31;

    // scores
#pragma unroll
    for (int qq = 0; qq < 2; qq++) {
        int q = w * 2 + qq;
        const float4* q4 = (const float4*)(sQ + q * 64);
        for (int k = lane; k < 129; k += 32) {
            const float4* k4 = (const float4*)(sK + k * KVP);
            float4 a = make_float4(0.f, 0.f, 0.f, 0.f);
#pragma unroll
            for (int j = 0; j < 16; j++) {
                float4 qv = q4[j], kv = k4[j];
                a.x = fmaf(qv.x, kv.x, a.x);
                a.y = fmaf(qv.y, kv.y, a.y);
                a.z = fmaf(qv.z, kv.z, a.z);
                a.w = fmaf(qv.w, kv.w, a.w);
            }
            sS[q * 132 + k] = (a.x + a.y + a.z + a.w) * 0.125f;
        }
    }
    __syncthreads();

    // softmax
#pragma unroll
    for (int qq = 0; qq < 2; qq++) {
        int q = w * 2 + qq;
        float mx = -CUDART_INF_F;
        for (int k = lane; k < 129; k += 32) mx = fmaxf(mx, sS[q * 132 + k]);
        mx = warp_max(mx);
        float s = 0.f;
        for (int k = lane; k < 129; k += 32) {
            float e = __expf(sS[q * 132 + k] - mx);
            sS[q * 132 + k] = e;
            s += e;
        }
        s = warp_sum(s);
        float inv = 1.f / s;
        for (int k = lane; k < 129; k += 32) sS[q * 132 + k] *= inv;
    }
    __syncthreads();

    // attn @ V : thread = (q, d4)
    int q = tid >> 4, d4 = tid & 15;
    {
        float4 acc = make_float4(0.f, 0.f, 0.f, 0.f);
        const float4* V4 = (const float4*)sV;
        const float* Sr = sS + q * 132;
#pragma unroll 4
        for (int k = 0; k < 129; k++) {
            float a = Sr[k];
            float4 v = V4[k * 17 + d4];
            acc.x = fmaf(a, v.x, acc.x);
            acc.y = fmaf(a, v.y, acc.y);
            acc.z = fmaf(a, v.z, acc.z);
            acc.w = fmaf(a, v.w, acc.w);
        }
        ((float4*)sO)[q * 17 + d4] = acc;
    }
    __syncthreads();

    // @ Wo + bo + residual
    {
        float4 acc = ((const float4*)sbo)[d4];
        const float* Or = sO + q * KVP;
        const float4* W4 = (const float4*)sWo;
#pragma unroll 8
        for (int j = 0; j < 64; j++) {
            float o = Or[j];
            float4 wv = W4[j * 16 + d4];
            acc.x = fmaf(o, wv.x, acc.x);
            acc.y = fmaf(o, wv.y, acc.y);
            acc.z = fmaf(o, wv.z, acc.z);
            acc.w = fmaf(o, wv.w, acc.w);
        }
        size_t off4 = ((size_t)b * 129 + 1 + q0 + q) * 16 + d4;
        float4 res = ((const float4*)g_kv)[off4];
        ((float4*)out)[off4] = make_float4(res.x + acc.x, res.y + acc.y,
                                           res.z + acc.z, res.w + acc.w);
    }

    // ---- fused target row: last block of this batch ----
    __threadfence();
    __syncthreads();
    if (tid == 0) sflag = (atomicAdd(&g_cnt[b], 1) == 3) ? 1 : 0;
    __syncthreads();
    if (!sflag) return;
    __threadfence();

    // load updated map emb (128 rows) into sK region
    const float4* out4 = (const float4*)out;
    for (int t = tid; t < 128 * 16; t += 512) {
        int r = t >> 4, dd4 = t & 15;
        ((float4*)sK)[r * 17 + dd4] = out4[((size_t)b * 129 + 1 + r) * 16 + dd4];
    }
    if (tid < 64) sQ[tid] = g_u[b * 64 + tid];
    __syncthreads();

    float c = g_csc[b];
    float sk = 0.f;
    if (tid < 128) {
        const float4* m4 = (const float4*)(sK + tid * KVP);
        const float4* u4 = (const float4*)sQ;
        float4 a = make_float4(0.f, 0.f, 0.f, 0.f);
#pragma unroll
        for (int j = 0; j < 16; j++) {
            float4 m = m4[j], u = u4[j];
            a.x = fmaf(m.x, u.x, a.x);
            a.y = fmaf(m.y, u.y, a.y);
            a.z = fmaf(m.z, u.z, a.z);
            a.w = fmaf(m.w, u.w, a.w);
        }
        sk = (a.x + a.y + a.z + a.w + c) * 0.125f;
    }
    // block softmax over 128 lanes (warps 0..3)
    float mx = warp_max(sk);
    if (tid < 128 && (tid & 31) == 0) sred[tid >> 5] = mx;
    __syncthreads();
    mx = fmaxf(fmaxf(sred[0], sred[1]), fmaxf(sred[2], sred[3]));
    float ex = (tid < 128) ? __expf(sk - mx) : 0.f;
    float ss = warp_sum(ex);
    if (tid < 128 && (tid & 31) == 0) sred[4 + (tid >> 5)] = ss;
    __syncthreads();
    float tot = sred[4] + sred[5] + sred[6] + sred[7];
    if (tid < 128) sS[tid] = ex / tot;
    __syncthreads();

    // w[d] = sum_k a_k * me[k][d]
    if (tid < 64) {
        float acc = 0.f;
#pragma unroll 4
        for (int k = 0; k < 128; k++)
            acc = fmaf(sS[k], sK[k * KVP + tid], acc);
        sQ[64 + tid] = acc;
    }
    __syncthreads();

    // out row0 = ta + w @ M2 + c2
    if (tid < 64) {
        float acc = g_ta[b * 64 + tid] + g_c2[tid];
        const float* wv = sQ + 64;
#pragma unroll 8
        for (int j = 0; j < 64; j++)
            acc = fmaf(wv[j], g_M2[j * 64 + tid], acc);
        out[(size_t)b * 129 * 64 + tid] = acc;
    }
}

// ============================================================
extern "C" void kernel_launch(void* const* d_in, const int* in_sizes, int n_in,
                              void* d_out, int out_size)
{
    const float* map_states   = (const float*)d_in[0];
    const float* agent_states = (const float*)d_in[1];
    const float* m_W1 = (const float*)d_in[2];
    const float* m_b1 = (const float*)d_in[3];
    const float* m_g1 = (const float*)d_in[4];
    const float* m_be1= (const float*)d_in[5];
    const float* m_W2 = (const float*)d_in[6];
    const float* m_b2 = (const float*)d_in[7];
    const float* m_g2 = (const float*)d_in[8];
    const float* m_be2= (const float*)d_in[9];
    const float* a_W1 = (const float*)d_in[10];
    const float* a_b1 = (const float*)d_in[11];
    const float* a_g1 = (const float*)d_in[12];
    const float* a_be1= (const float*)d_in[13];
    const float* a_W2 = (const float*)d_in[14];
    const float* a_b2 = (const float*)d_in[15];
    const float* a_g2 = (const float*)d_in[16];
    const float* a_be2= (const float*)d_in[17];
    const float* att_Wq = (const float*)d_in[18];
    const float* att_bq = (const float*)d_in[19];
    const float* att_Wk = (const float*)d_in[20];
    const float* att_bk = (const float*)d_in[21];
    const float* att_Wv = (const float*)d_in[22];
    const float* att_bv = (const float*)d_in[23];
    const float* att_Wo = (const float*)d_in[24];
    const float* att_bo = (const float*)d_in[25];
    float* out = (float*)d_out;

    cudaFuncSetAttribute(k_attn, cudaFuncAttributeMaxDynamicSharedMemorySize,
                         ATTN_SMEM_BYTES);
    cudaFuncSetAttribute(k_proj, cudaFuncAttributeMaxDynamicSharedMemorySize,
                         PROJ_SMEM_BYTES);

    k_graph<<<1072, dim3(32, 20)>>>(
        map_states, m_W1, m_b1, m_g1, m_be1, m_W2, m_b2, m_g2, m_be2,
        agent_states, a_W1, a_b1, a_g1, a_be1, a_W2, a_b2, a_g2, a_be2,
        att_Wv, att_bv, att_Wo, att_bo);

    k_proj<<<dim3(10, 32), 256, PROJ_SMEM_BYTES>>>(
        att_Wq + 0 * 4096, att_bq + 0 * 64,
        att_Wk + 0 * 4096, att_bk + 0 * 64,
        att_Wv + 0 * 4096, att_bv + 0 * 64,
        att_Wq + 2 * 4096, att_bq + 2 * 64,
        att_Wk + 2 * 4096, att_bk + 2 * 64);

    k_attn<<<dim3(4, 32), 512, ATTN_SMEM_BYTES>>>(
        att_Wo + 0 * 4096, att_bo + 0 * 64, out);
}

// round 5
// speedup vs baseline: 2.0480x; 1.3786x over previous
#include <cuda_runtime.h>
#include <math.h>
#include <math_constants.h>

#define FULL 0xffffffffu

__device__ __forceinline__ float warp_sum(float v) {
#pragma unroll
    for (int o = 16; o > 0; o >>= 1) v += __shfl_xor_sync(FULL, v, o);
    return v;
}
__device__ __forceinline__ float warp_max(float v) {
#pragma unroll
    for (int o = 16; o > 0; o >>= 1) v = fmaxf(v, __shfl_xor_sync(FULL, v, o));
    return v;
}

// ---- scratch (allocation-free: __device__ globals) ----
__device__ float g_kv[32 * 129 * 64];   // row 0: target emb, rows 1..128: map emb
__device__ float g_Q[32 * 128 * 64];
__device__ float g_K[32 * 129 * 64];
__device__ float g_V[32 * 129 * 64];
__device__ float g_M1[64 * 64], g_c1[64];   // Wv1@Wo1, bv1@Wo1+bo1
__device__ float g_M2[64 * 64], g_c2[64];   // Wv2@Wo2, bv2@Wo2+bo2
__device__ float g_ta[32 * 64];             // t_a per batch
__device__ float g_u[32 * 64];              // folded K-projection vector
__device__ float g_csc[32];                 // Q2 . bk2
__device__ int   g_cnt[32];                 // last-block counter (reset in k_proj)

// in-thread LayerNorm + affine + relu over 32 register channels
__device__ __forceinline__ void ln_relu32(float* h, const float* g, const float* be) {
    float s = 0.f;
#pragma unroll
    for (int c = 0; c < 32; c++) s += h[c];
    float mu = s * 0.03125f;
    float v = 0.f;
#pragma unroll
    for (int c = 0; c < 32; c++) { float d = h[c] - mu; v = fmaf(d, d, v); }
    float rs = rsqrtf(v * 0.03125f + 1e-5f);
#pragma unroll
    for (int c = 0; c < 32; c++)
        h[c] = fmaxf(fmaf((h[c] - mu) * rs, g[c], be[c]), 0.f);
}

// ============================================================
// Kernel 1: local graphs (thread-per-row, shuffle-free) + weight folds.
//   blocks [0,256): map rows, 320 rows/block (16 (b,m) groups x 20)
//   [256,260): agent rows, 8 batches x 32 rows per block
//   [260,276): M1/M2 = Wv@Wo folds + c1/c2
// ============================================================
constexpr int GRAPH_SMEM_FLOATS = 1792 + 320 * 36;
constexpr int GRAPH_SMEM_BYTES  = GRAPH_SMEM_FLOATS * 4;

__global__ __launch_bounds__(320) void k_graph(
    const float* __restrict__ mxs,
    const float* __restrict__ mW1, const float* __restrict__ mb1,
    const float* __restrict__ mg1, const float* __restrict__ mbe1,
    const float* __restrict__ mW2, const float* __restrict__ mb2,
    const float* __restrict__ mg2, const float* __restrict__ mbe2,
    const float* __restrict__ axs,
    const float* __restrict__ aW1, const float* __restrict__ ab1,
    const float* __restrict__ ag1, const float* __restrict__ abe1,
    const float* __restrict__ aW2, const float* __restrict__ ab2,
    const float* __restrict__ ag2, const float* __restrict__ abe2,
    const float* __restrict__ att_Wv, const float* __restrict__ att_bv,
    const float* __restrict__ att_Wo, const float* __restrict__ att_bo)
{
    extern __shared__ float sm[];
    int tid = threadIdx.x;
    int bb = blockIdx.x;

    if (bb < 256) {
        // ---------------- map path: thread = one (b,m,p) row ----------------
        float* sW1 = sm;            // 16*32 = 512
        float* sW2 = sm + 512;      // 32*32 = 1024
        float* sb1 = sm + 1536; float* sg1 = sm + 1568; float* sbe1 = sm + 1600;
        float* sb2 = sm + 1632; float* sg2 = sm + 1664; float* sbe2 = sm + 1696;
        float* se  = sm + 1792;     // 320*36

        if (tid < 128) ((float4*)sW1)[tid] = ((const float4*)mW1)[tid];
        // FIX (round-4 bug): sW2 has 256 float4s; strided loop covers all of them
        for (int t = tid; t < 256; t += 320)
            ((float4*)sW2)[t] = ((const float4*)mW2)[t];
        if (tid >= 128 && tid < 160) {
            int c = tid - 128;
            sb1[c] = mb1[c]; sg1[c] = mg1[c]; sbe1[c] = mbe1[c];
            sb2[c] = mb2[c]; sg2[c] = mg2[c]; sbe2[c] = mbe2[c];
        }
        __syncthreads();

        size_t row = (size_t)bb * 320 + tid;
        float x[16];
        {
            const float4* xg = (const float4*)(mxs + row * 16);
            float4 a = xg[0], b_ = xg[1], c = xg[2], d = xg[3];
            x[0]=a.x; x[1]=a.y; x[2]=a.z; x[3]=a.w;
            x[4]=b_.x; x[5]=b_.y; x[6]=b_.z; x[7]=b_.w;
            x[8]=c.x; x[9]=c.y; x[10]=c.z; x[11]=c.w;
            x[12]=d.x; x[13]=d.y; x[14]=d.z; x[15]=d.w;
        }

        float h[32];
#pragma unroll
        for (int c4 = 0; c4 < 8; c4++) {
            float4 b4 = ((const float4*)sb1)[c4];
            h[c4*4+0]=b4.x; h[c4*4+1]=b4.y; h[c4*4+2]=b4.z; h[c4*4+3]=b4.w;
        }
#pragma unroll
        for (int k = 0; k < 16; k++) {
            float xv = x[k];
#pragma unroll
            for (int c4 = 0; c4 < 8; c4++) {
                float4 w = ((const float4*)sW1)[k * 8 + c4];
                h[c4*4+0] = fmaf(xv, w.x, h[c4*4+0]);
                h[c4*4+1] = fmaf(xv, w.y, h[c4*4+1]);
                h[c4*4+2] = fmaf(xv, w.z, h[c4*4+2]);
                h[c4*4+3] = fmaf(xv, w.w, h[c4*4+3]);
            }
        }
        ln_relu32(h, sg1, sbe1);

        float a2[32];
#pragma unroll
        for (int c4 = 0; c4 < 8; c4++) {
            float4 b4 = ((const float4*)sb2)[c4];
            a2[c4*4+0]=b4.x; a2[c4*4+1]=b4.y; a2[c4*4+2]=b4.z; a2[c4*4+3]=b4.w;
        }
#pragma unroll
        for (int k = 0; k < 32; k++) {
            float hv = h[k];
#pragma unroll
            for (int c4 = 0; c4 < 8; c4++) {
                float4 w = ((const float4*)sW2)[k * 8 + c4];
                a2[c4*4+0] = fmaf(hv, w.x, a2[c4*4+0]);
                a2[c4*4+1] = fmaf(hv, w.y, a2[c4*4+1]);
                a2[c4*4+2] = fmaf(hv, w.z, a2[c4*4+2]);
                a2[c4*4+3] = fmaf(hv, w.w, a2[c4*4+3]);
            }
        }
        ln_relu32(a2, sg2, sbe2);

#pragma unroll
        for (int c4 = 0; c4 < 8; c4++)
            ((float4*)(se + tid * 36))[c4] =
                make_float4(a2[c4*4+0], a2[c4*4+1], a2[c4*4+2], a2[c4*4+3]);
        __syncthreads();

        // max over the 20 rows of each group: warp w -> groups w, w+10
        int w = tid >> 5, lane = tid & 31;
        for (int g = w; g < 16; g += 10) {
            const float* base = se + (g * 20) * 36 + lane;
            float mx = base[0];
#pragma unroll
            for (int j = 1; j < 20; j++) mx = fmaxf(mx, base[j * 36]);
            int bm = bb * 16 + g;
            int b = bm >> 7, m = bm & 127;
            float* dst = g_kv + ((size_t)b * 129 + 1 + m) * 64;
            dst[lane] = mx;
            dst[32 + lane] = mx;
        }
    } else if (bb < 260) {
        // ---------------- agent path (agent 0): thread = one (b,t) row ----------------
        float* aW1s = sm;           // 4*32 = 128
        float* aW2s = sm + 512;     // 32*32 = 1024
        float* ab1s = sm + 1536; float* ag1s = sm + 1568; float* abe1s = sm + 1600;
        float* ab2s = sm + 1632; float* ag2s = sm + 1664; float* abe2s = sm + 1696;
        float* se   = sm + 1792;    // 256*36

        if (tid < 32) ((float4*)aW1s)[tid] = ((const float4*)aW1)[tid];
        else if (tid < 288) ((float4*)aW2s)[tid - 32] = ((const float4*)aW2)[tid - 32];
        if (tid >= 288) {
            int t = tid - 288; // 0..31
            ab1s[t] = ab1[t]; ag1s[t] = ag1[t]; abe1s[t] = abe1[t];
            ab2s[t] = ab2[t]; ag2s[t] = ag2[t]; abe2s[t] = abe2[t];
        }
        __syncthreads();

        if (tid < 256) {
            int b0 = (bb - 256) * 8;
            int lb = tid >> 5, row = tid & 31;
            int b = b0 + lb;
            float4 xv4 = ((const float4*)(axs + (size_t)b * 4096 + row * 4))[0];

            float h[32];
#pragma unroll
            for (int c4 = 0; c4 < 8; c4++) {
                float4 b4 = ((const float4*)ab1s)[c4];
                h[c4*4+0]=b4.x; h[c4*4+1]=b4.y; h[c4*4+2]=b4.z; h[c4*4+3]=b4.w;
            }
            float xk[4] = {xv4.x, xv4.y, xv4.z, xv4.w};
#pragma unroll
            for (int k = 0; k < 4; k++) {
                float xv = xk[k];
#pragma unroll
                for (int c4 = 0; c4 < 8; c4++) {
                    float4 w = ((const float4*)aW1s)[k * 8 + c4];
                    h[c4*4+0] = fmaf(xv, w.x, h[c4*4+0]);
                    h[c4*4+1] = fmaf(xv, w.y, h[c4*4+1]);
                    h[c4*4+2] = fmaf(xv, w.z, h[c4*4+2]);
                    h[c4*4+3] = fmaf(xv, w.w, h[c4*4+3]);
                }
            }
            ln_relu32(h, ag1s, abe1s);

            float a2[32];
#pragma unroll
            for (int c4 = 0; c4 < 8; c4++) {
                float4 b4 = ((const float4*)ab2s)[c4];
                a2[c4*4+0]=b4.x; a2[c4*4+1]=b4.y; a2[c4*4+2]=b4.z; a2[c4*4+3]=b4.w;
            }
#pragma unroll
            for (int k = 0; k < 32; k++) {
                float hv = h[k];
#pragma unroll
                for (int c4 = 0; c4 < 8; c4++) {
                    float4 w = ((const float4*)aW2s)[k * 8 + c4];
                    a2[c4*4+0] = fmaf(hv, w.x, a2[c4*4+0]);
                    a2[c4*4+1] = fmaf(hv, w.y, a2[c4*4+1]);
                    a2[c4*4+2] = fmaf(hv, w.z, a2[c4*4+2]);
                    a2[c4*4+3] = fmaf(hv, w.w, a2[c4*4+3]);
                }
            }
            ln_relu32(a2, ag2s, abe2s);

#pragma unroll
            for (int c4 = 0; c4 < 8; c4++)
                ((float4*)(se + tid * 36))[c4] =
                    make_float4(a2[c4*4+0], a2[c4*4+1], a2[c4*4+2], a2[c4*4+3]);
        }
        __syncthreads();

        // warp w (0..7) reduces batch b0+w over 32 rows
        int w = tid >> 5, lane = tid & 31;
        if (w < 8) {
            const float* base = se + (w * 32) * 36 + lane;
            float mx = base[0];
#pragma unroll
            for (int j = 1; j < 32; j++) mx = fmaxf(mx, base[j * 36]);
            int b = (bb - 256) * 8 + w;
            float* dst = g_kv + (size_t)b * 129 * 64;
            dst[lane] = mx;
            dst[32 + lane] = mx;
        }
    } else {
        // ---------------- weight-fold: M = Wv@Wo, c = bv@Wo + bo ----------------
        float* sWo = sm;            // 4096
        float* sWv = sm + 4096;     // 512

        int which = bb - 260;             // 0..15
        int head  = 1 + (which >> 3);     // 1 or 2
        int r0    = (which & 7) * 8;
        const float* Wv = att_Wv + head * 4096;
        const float* Wo = att_Wo + head * 4096;
        const float* bv = att_bv + head * 64;
        const float* bo = att_bo + head * 64;
        float* M    = (head == 1) ? g_M1 : g_M2;
        float* cvec = (head == 1) ? g_c1 : g_c2;

        for (int t = tid; t < 1024; t += 320)
            ((float4*)sWo)[t] = ((const float4*)Wo)[t];
        if (tid < 128)
            ((float4*)sWv)[tid] = ((const float4*)(Wv + r0 * 64))[tid];
        __syncthreads();

        for (int t = tid; t < 512; t += 320) {
            int r = t >> 6, d = t & 63;
            float acc = 0.f;
#pragma unroll 8
            for (int k = 0; k < 64; k++)
                acc = fmaf(sWv[r * 64 + k], sWo[k * 64 + d], acc);
            M[(r0 + r) * 64 + d] = acc;
        }
        if (r0 == 0 && tid < 64) {
            int d = tid;
            float acc = bo[d];
#pragma unroll 8
            for (int k = 0; k < 64; k++)
                acc = fmaf(bv[k], sWo[k * 64 + d], acc);
            cvec[d] = acc;
        }
    }
}

// ============================================================
// Kernel 2: Q/K/V projection (blocks x<9) + target precompute (x==9).
// ============================================================
constexpr int PROJ_SMEM_FLOATS = 3 * 4096 + 16 * 64 + 3 * 64;
constexpr int PROJ_SMEM_BYTES = PROJ_SMEM_FLOATS * 4;

__global__ __launch_bounds__(256) void k_proj(
    const float* __restrict__ Wq, const float* __restrict__ bq,
    const float* __restrict__ Wk, const float* __restrict__ bk,
    const float* __restrict__ Wv, const float* __restrict__ bv,
    const float* __restrict__ Wq2, const float* __restrict__ bq2,
    const float* __restrict__ Wk2, const float* __restrict__ bk2)
{
    extern __shared__ float psm[];
    int b  = blockIdx.y;
    int tid = threadIdx.x;

    if (blockIdx.x < 9) {
        float* sW = psm;              // 3 * 4096
        float* sx = sW + 12288;       // 16 * 64
        float* sb = sx + 1024;        // 3 * 64
        int r0 = blockIdx.x * 16;

        for (int t = tid; t < 1024; t += 256) {
            ((float4*)sW)[t]        = ((const float4*)Wq)[t];
            ((float4*)sW)[1024 + t] = ((const float4*)Wk)[t];
            ((float4*)sW)[2048 + t] = ((const float4*)Wv)[t];
        }
        if (tid < 64) { sb[tid] = bq[tid]; sb[64 + tid] = bk[tid]; sb[128 + tid] = bv[tid]; }
        {
            int rl = tid >> 4, d4 = tid & 15;
            int r = r0 + rl;
            float4 v = make_float4(0.f, 0.f, 0.f, 0.f);
            if (r < 129) v = ((const float4*)g_kv)[((size_t)b * 129 + r) * 16 + d4];
            ((float4*)sx)[tid] = v;
        }
        __syncthreads();

        int rl = tid >> 4, d4 = tid & 15;
        int r = r0 + rl;

#pragma unroll
        for (int p = 0; p < 3; p++) {
            if (r < 129 && !(p == 0 && r == 0)) {
                float4 acc = ((const float4*)sb)[p * 16 + d4];
                const float* xr = sx + rl * 64;
                const float4* W4 = (const float4*)sW + p * 1024;
#pragma unroll 8
                for (int j = 0; j < 64; j++) {
                    float x = xr[j];
                    float4 w = W4[j * 16 + d4];
                    acc.x = fmaf(x, w.x, acc.x);
                    acc.y = fmaf(x, w.y, acc.y);
                    acc.z = fmaf(x, w.z, acc.z);
                    acc.w = fmaf(x, w.w, acc.w);
                }
                if (p == 0)      ((float4*)g_Q)[((size_t)b * 128 + (r - 1)) * 16 + d4] = acc;
                else if (p == 1) ((float4*)g_K)[((size_t)b * 129 + r) * 16 + d4] = acc;
                else             ((float4*)g_V)[((size_t)b * 129 + r) * 16 + d4] = acc;
            }
        }
    } else {
        // ---- target precompute for batch b ----
        float* sW  = psm;             // 4096 (Wq2 staging)
        float* st  = sW + 4096;       // 64
        float* sQ2 = st + 64;         // 64
        float* sp  = sQ2 + 64;        // 4 * 64 partials

        if (tid < 64) st[tid] = g_kv[(size_t)b * 129 * 64 + tid];
        for (int t = tid; t < 1024; t += 256)
            ((float4*)sW)[t] = ((const float4*)Wq2)[t];
        __syncthreads();

        int d = tid & 63, p = tid >> 6;
        {
            float acc = 0.f;
#pragma unroll
            for (int j = p * 16; j < p * 16 + 16; j++)
                acc = fmaf(st[j], sW[j * 64 + d], acc);
            sp[p * 64 + d] = acc;
        }
        __syncthreads();
        if (tid < 64)
            sQ2[tid] = bq2[tid] + sp[tid] + sp[64 + tid] + sp[128 + tid] + sp[192 + tid];
        __syncthreads();

        // c = Q2 . bk2
        if (tid < 32) {
            float a = 0.f;
            for (int dd = tid; dd < 64; dd += 32) a = fmaf(sQ2[dd], bk2[dd], a);
            a = warp_sum(a);
            if (tid == 0) g_csc[b] = a;
        }

        // u[j] = Wk2[j,:] . Q2  (warp per 8 rows, coalesced gmem reads)
        {
            int w = tid >> 5, lane = tid & 31;
            for (int j = w * 8; j < w * 8 + 8; j++) {
                float a = sQ2[lane] * Wk2[j * 64 + lane];
                a = fmaf(sQ2[lane + 32], Wk2[j * 64 + lane + 32], a);
                a = warp_sum(a);
                if (lane == 0) g_u[b * 64 + j] = a;
            }
        }

        // ta = t @ M1 + c1
        if (tid < 64) {
            float acc = g_c1[tid];
#pragma unroll 8
            for (int j = 0; j < 64; j++)
                acc = fmaf(st[j], g_M1[j * 64 + tid], acc);
            g_ta[b * 64 + tid] = acc;
        }

        if (tid == 0) g_cnt[b] = 0;   // reset last-block counter for this launch
    }
}

// ============================================================
// Kernel 3: a2m attention + Wo + residual; last block per batch
// also computes the target row (fused former k_target).
// ============================================================
#define KVP 68
constexpr int ATTN_SMEM_FLOATS =
    129 * KVP      // sK (reused as me-tile in target phase)
  + 129 * KVP      // sV
  + 32 * 64        // sQ (reused as u/w in target phase)
  + 32 * 132       // sS (reused as probs in target phase)
  + 32 * KVP       // sO
  + 64 * 64        // sWo
  + 64;            // sbo
constexpr int ATTN_SMEM_BYTES = ATTN_SMEM_FLOATS * 4;

__global__ __launch_bounds__(512) void k_attn(
    const float* __restrict__ Wo, const float* __restrict__ bo,
    float* __restrict__ out)
{
    extern __shared__ float smem[];
    float* sK  = smem;
    float* sV  = sK + 129 * KVP;
    float* sQ  = sV + 129 * KVP;
    float* sS  = sQ + 32 * 64;
    float* sO  = sS + 32 * 132;
    float* sWo = sO + 32 * KVP;
    float* sbo = sWo + 64 * 64;
    __shared__ int sflag;
    __shared__ float sred[8];

    int b  = blockIdx.y;
    int q0 = blockIdx.x * 32;
    int tid = threadIdx.x;

    const float4* K4g = (const float4*)(g_K + (size_t)b * 129 * 64);
    const float4* V4g = (const float4*)(g_V + (size_t)b * 129 * 64);
    for (int t = tid; t < 129 * 16; t += 512) {
        int r = t >> 4, d4 = t & 15;
        ((float4*)sK)[r * 17 + d4] = K4g[t];
        ((float4*)sV)[r * 17 + d4] = V4g[t];
    }
    ((float4*)sQ)[tid] = ((const float4*)(g_Q + (size_t)b * 128 * 64))[q0 * 16 + tid];
    for (int t = tid; t < 1024; t += 512) ((float4*)sWo)[t] = ((const float4*)Wo)[t];
    if (tid < 64) sbo[tid] = bo[tid];
    __syncthreads();

    int w = tid >> 5, lane = tid & 31;

    // scores
#pragma unroll
    for (int qq = 0; qq < 2; qq++) {
        int q = w * 2 + qq;
        const float4* q4 = (const float4*)(sQ + q * 64);
        for (int k = lane; k < 129; k += 32) {
            const float4* k4 = (const float4*)(sK + k * KVP);
            float4 a = make_float4(0.f, 0.f, 0.f, 0.f);
#pragma unroll
            for (int j = 0; j < 16; j++) {
                float4 qv = q4[j], kv = k4[j];
                a.x = fmaf(qv.x, kv.x, a.x);
                a.y = fmaf(qv.y, kv.y, a.y);
                a.z = fmaf(qv.z, kv.z, a.z);
                a.w = fmaf(qv.w, kv.w, a.w);
            }
            sS[q * 132 + k] = (a.x + a.y + a.z + a.w) * 0.125f;
        }
    }
    __syncthreads();

    // softmax
#pragma unroll
    for (int qq = 0; qq < 2; qq++) {
        int q = w * 2 + qq;
        float mx = -CUDART_INF_F;
        for (int k = lane; k < 129; k += 32) mx = fmaxf(mx, sS[q * 132 + k]);
        mx = warp_max(mx);
        float s = 0.f;
        for (int k = lane; k < 129; k += 32) {
            float e = __expf(sS[q * 132 + k] - mx);
            sS[q * 132 + k] = e;
            s += e;
        }
        s = warp_sum(s);
        float inv = 1.f / s;
        for (int k = lane; k < 129; k += 32) sS[q * 132 + k] *= inv;
    }
    __syncthreads();

    // attn @ V : thread = (q, d4)
    int q = tid >> 4, d4 = tid & 15;
    {
        float4 acc = make_float4(0.f, 0.f, 0.f, 0.f);
        const float4* V4 = (const float4*)sV;
        const float* Sr = sS + q * 132;
#pragma unroll 4
        for (int k = 0; k < 129; k++) {
            float a = Sr[k];
            float4 v = V4[k * 17 + d4];
            acc.x = fmaf(a, v.x, acc.x);
            acc.y = fmaf(a, v.y, acc.y);
            acc.z = fmaf(a, v.z, acc.z);
            acc.w = fmaf(a, v.w, acc.w);
        }
        ((float4*)sO)[q * 17 + d4] = acc;
    }
    __syncthreads();

    // @ Wo + bo + residual
    {
        float4 acc = ((const float4*)sbo)[d4];
        const float* Or = sO + q * KVP;
        const float4* W4 = (const float4*)sWo;
#pragma unroll 8
        for (int j = 0; j < 64; j++) {
            float o = Or[j];
            float4 wv = W4[j * 16 + d4];
            acc.x = fmaf(o, wv.x, acc.x);
            acc.y = fmaf(o, wv.y, acc.y);
            acc.z = fmaf(o, wv.z, acc.z);
            acc.w = fmaf(o, wv.w, acc.w);
        }
        size_t off4 = ((size_t)b * 129 + 1 + q0 + q) * 16 + d4;
        float4 res = ((const float4*)g_kv)[off4];
        ((float4*)out)[off4] = make_float4(res.x + acc.x, res.y + acc.y,
                                           res.z + acc.z, res.w + acc.w);
    }

    // ---- fused target row: last block of this batch ----
    __threadfence();
    __syncthreads();
    if (tid == 0) sflag = (atomicAdd(&g_cnt[b], 1) == 3) ? 1 : 0;
    __syncthreads();
    if (!sflag) return;
    __threadfence();

    // load updated map emb (128 rows) into sK region
    const float4* out4 = (const float4*)out;
    for (int t = tid; t < 128 * 16; t += 512) {
        int r = t >> 4, dd4 = t & 15;
        ((float4*)sK)[r * 17 + dd4] = out4[((size_t)b * 129 + 1 + r) * 16 + dd4];
    }
    if (tid < 64) sQ[tid] = g_u[b * 64 + tid];
    __syncthreads();

    float c = g_csc[b];
    float sk = 0.f;
    if (tid < 128) {
        const float4* m4 = (const float4*)(sK + tid * KVP);
        const float4* u4 = (const float4*)sQ;
        float4 a = make_float4(0.f, 0.f, 0.f, 0.f);
#pragma unroll
        for (int j = 0; j < 16; j++) {
            float4 m = m4[j], u = u4[j];
            a.x = fmaf(m.x, u.x, a.x);
            a.y = fmaf(m.y, u.y, a.y);
            a.z = fmaf(m.z, u.z, a.z);
            a.w = fmaf(m.w, u.w, a.w);
        }
        sk = (a.x + a.y + a.z + a.w + c) * 0.125f;
    }
    // block softmax over 128 lanes (warps 0..3)
    float mx = warp_max(sk);
    if (tid < 128 && (tid & 31) == 0) sred[tid >> 5] = mx;
    __syncthreads();
    mx = fmaxf(fmaxf(sred[0], sred[1]), fmaxf(sred[2], sred[3]));
    float ex = (tid < 128) ? __expf(sk - mx) : 0.f;
    float ss = warp_sum(ex);
    if (tid < 128 && (tid & 31) == 0) sred[4 + (tid >> 5)] = ss;
    __syncthreads();
    float tot = sred[4] + sred[5] + sred[6] + sred[7];
    if (tid < 128) sS[tid] = ex / tot;
    __syncthreads();

    // w[d] = sum_k a_k * me[k][d]
    if (tid < 64) {
        float acc = 0.f;
#pragma unroll 4
        for (int k = 0; k < 128; k++)
            acc = fmaf(sS[k], sK[k * KVP + tid], acc);
        sQ[64 + tid] = acc;
    }
    __syncthreads();

    // out row0 = ta + w @ M2 + c2
    if (tid < 64) {
        float acc = g_ta[b * 64 + tid] + g_c2[tid];
        const float* wv = sQ + 64;
#pragma unroll 8
        for (int j = 0; j < 64; j++)
            acc = fmaf(wv[j], g_M2[j * 64 + tid], acc);
        out[(size_t)b * 129 * 64 + tid] = acc;
    }
}

// ============================================================
extern "C" void kernel_launch(void* const* d_in, const int* in_sizes, int n_in,
                              void* d_out, int out_size)
{
    const float* map_states   = (const float*)d_in[0];
    const float* agent_states = (const float*)d_in[1];
    const float* m_W1 = (const float*)d_in[2];
    const float* m_b1 = (const float*)d_in[3];
    const float* m_g1 = (const float*)d_in[4];
    const float* m_be1= (const float*)d_in[5];
    const float* m_W2 = (const float*)d_in[6];
    const float* m_b2 = (const float*)d_in[7];
    const float* m_g2 = (const float*)d_in[8];
    const float* m_be2= (const float*)d_in[9];
    const float* a_W1 = (const float*)d_in[10];
    const float* a_b1 = (const float*)d_in[11];
    const float* a_g1 = (const float*)d_in[12];
    const float* a_be1= (const float*)d_in[13];
    const float* a_W2 = (const float*)d_in[14];
    const float* a_b2 = (const float*)d_in[15];
    const float* a_g2 = (const float*)d_in[16];
    const float* a_be2= (const float*)d_in[17];
    const float* att_Wq = (const float*)d_in[18];
    const float* att_bq = (const float*)d_in[19];
    const float* att_Wk = (const float*)d_in[20];
    const float* att_bk = (const float*)d_in[21];
    const float* att_Wv = (const float*)d_in[22];
    const float* att_bv = (const float*)d_in[23];
    const float* att_Wo = (const float*)d_in[24];
    const float* att_bo = (const float*)d_in[25];
    float* out = (float*)d_out;

    cudaFuncSetAttribute(k_graph, cudaFuncAttributeMaxDynamicSharedMemorySize,
                         GRAPH_SMEM_BYTES);
    cudaFuncSetAttribute(k_attn, cudaFuncAttributeMaxDynamicSharedMemorySize,
                         ATTN_SMEM_BYTES);
    cudaFuncSetAttribute(k_proj, cudaFuncAttributeMaxDynamicSharedMemorySize,
                         PROJ_SMEM_BYTES);

    k_graph<<<276, 320, GRAPH_SMEM_BYTES>>>(
        map_states, m_W1, m_b1, m_g1, m_be1, m_W2, m_b2, m_g2, m_be2,
        agent_states, a_W1, a_b1, a_g1, a_be1, a_W2, a_b2, a_g2, a_be2,
        att_Wv, att_bv, att_Wo, att_bo);

    k_proj<<<dim3(10, 32), 256, PROJ_SMEM_BYTES>>>(
        att_Wq + 0 * 4096, att_bq + 0 * 64,
        att_Wk + 0 * 4096, att_bk + 0 * 64,
        att_Wv + 0 * 4096, att_bv + 0 * 64,
        att_Wq + 2 * 4096, att_bq + 2 * 64,
        att_Wk + 2 * 4096, att_bk + 2 * 64);

    k_attn<<<dim3(4, 32), 512, ATTN_SMEM_BYTES>>>(
        att_Wo + 0 * 4096, att_bo + 0 * 64, out);
}